// round 2
// baseline (speedup 1.0000x reference)
#include <cuda_runtime.h>

// Problem constants
static constexpr int T_ = 2048;
static constexpr int B_ = 16;
static constexpr int D_ = 1024;
static constexpr int M_ = T_ * B_;    // 32768 rows
static constexpr int N_ = 3 * D_;     // 3072 cols
static constexpr int K_ = D_;         // 1024
static constexpr float EPS_ = 1e-5f;

// Scratch: pre-activation GEMM result and normalized/activated result.
// __device__ globals (no runtime allocation allowed).
__device__ float g_pre[(size_t)M_ * N_];   // ~402 MB
__device__ float g_post[(size_t)M_ * N_];  // ~402 MB

// ---------------------------------------------------------------------------
// Kernel 1: SGEMM  g_pre[r, o] = sum_k input[r, k] * W[k, o]
// 128x128 block tile, BK=16, 256 threads, 8x8 register tile per thread.
// ---------------------------------------------------------------------------
__global__ __launch_bounds__(256) void sgemm_kernel(const float* __restrict__ A,
                                                    const float* __restrict__ Bw) {
    constexpr int BM = 128, BN = 128, BK = 16, TM = 8, TN = 8;
    __shared__ float As[BK][BM];       // transposed A tile
    __shared__ float Bs[BK][BN];

    const int bx = blockIdx.x;         // N tile
    const int by = blockIdx.y;         // M tile
    const int tid = threadIdx.x;       // 0..255
    const int tx = tid % (BN / TN);    // 0..15
    const int ty = tid / (BN / TN);    // 0..15

    const float* Ab = A + (size_t)by * BM * K_;
    const float* Bb = Bw + (size_t)bx * BN;

    float acc[TM][TN];
#pragma unroll
    for (int i = 0; i < TM; i++)
#pragma unroll
        for (int j = 0; j < TN; j++) acc[i][j] = 0.f;

    for (int k0 = 0; k0 < K_; k0 += BK) {
        // Cooperative loads: 512 float4 per tile for A and B, 2 each per thread.
#pragma unroll
        for (int i = 0; i < 2; i++) {
            int idx = tid + i * 256;
            // A tile: 128 rows x 16 cols (4 float4 per row)
            int arow = idx >> 2;
            int acol = (idx & 3) * 4;
            float4 v = *(const float4*)(Ab + (size_t)arow * K_ + k0 + acol);
            As[acol + 0][arow] = v.x;
            As[acol + 1][arow] = v.y;
            As[acol + 2][arow] = v.z;
            As[acol + 3][arow] = v.w;
            // B tile: 16 rows x 128 cols (32 float4 per row)
            int brow = idx >> 5;
            int bcol = (idx & 31) * 4;
            float4 w = *(const float4*)(Bb + (size_t)(k0 + brow) * N_ + bcol);
            *(float4*)&Bs[brow][bcol] = w;
        }
        __syncthreads();

        float regM[TM], regN[TN];
#pragma unroll
        for (int kk = 0; kk < BK; kk++) {
#pragma unroll
            for (int i = 0; i < TM; i++) regM[i] = As[kk][ty * TM + i];
#pragma unroll
            for (int j = 0; j < TN; j++) regN[j] = Bs[kk][tx * TN + j];
#pragma unroll
            for (int i = 0; i < TM; i++)
#pragma unroll
                for (int j = 0; j < TN; j++) acc[i][j] += regM[i] * regN[j];
        }
        __syncthreads();
    }

    float* Cb = g_pre + (size_t)by * BM * N_ + (size_t)bx * BN;
#pragma unroll
    for (int i = 0; i < TM; i++) {
#pragma unroll
        for (int j = 0; j < TN; j += 4) {
            float4 v = make_float4(acc[i][j], acc[i][j + 1], acc[i][j + 2], acc[i][j + 3]);
            *(float4*)(Cb + (size_t)(ty * TM + i) * N_ + tx * TN + j) = v;
        }
    }
}

// ---------------------------------------------------------------------------
// Kernel 2: LayerNorm over last dim (3072) + affine + sigmoid on thirds 0 and 2.
// One block (256 threads) per row.
// ---------------------------------------------------------------------------
__device__ __forceinline__ float sigmoidf_(float y) {
    return 1.f / (1.f + __expf(-y));
}

__global__ __launch_bounds__(256) void ln_act_kernel(const float* __restrict__ gamma,
                                                     const float* __restrict__ beta) {
    const int r = blockIdx.x;
    const float* row = g_pre + (size_t)r * N_;
    float* orow = g_post + (size_t)r * N_;

    float sum = 0.f, sumsq = 0.f;
    for (int i = threadIdx.x; i < N_ / 4; i += 256) {
        float4 v = ((const float4*)row)[i];
        sum += v.x + v.y + v.z + v.w;
        sumsq += v.x * v.x + v.y * v.y + v.z * v.z + v.w * v.w;
    }
    __shared__ float s1[32], s2[32];
#pragma unroll
    for (int o = 16; o; o >>= 1) {
        sum += __shfl_down_sync(~0u, sum, o);
        sumsq += __shfl_down_sync(~0u, sumsq, o);
    }
    int w = threadIdx.x >> 5, l = threadIdx.x & 31;
    if (!l) { s1[w] = sum; s2[w] = sumsq; }
    __syncthreads();
    if (w == 0) {
        sum = (l < 8) ? s1[l] : 0.f;
        sumsq = (l < 8) ? s2[l] : 0.f;
#pragma unroll
        for (int o = 4; o; o >>= 1) {
            sum += __shfl_down_sync(~0u, sum, o);
            sumsq += __shfl_down_sync(~0u, sumsq, o);
        }
        if (!l) {
            float mu = sum * (1.f / N_);
            float var = sumsq * (1.f / N_) - mu * mu;
            s1[0] = mu;
            s2[0] = rsqrtf(var + EPS_);
        }
    }
    __syncthreads();
    const float mu = s1[0], inv = s2[0];

    for (int i = threadIdx.x; i < N_ / 4; i += 256) {
        float4 v = ((const float4*)row)[i];
        float4 gm = ((const float4*)gamma)[i];
        float4 bt = ((const float4*)beta)[i];
        float4 y;
        y.x = (v.x - mu) * inv * gm.x + bt.x;
        y.y = (v.y - mu) * inv * gm.y + bt.y;
        y.z = (v.z - mu) * inv * gm.z + bt.z;
        y.w = (v.w - mu) * inv * gm.w + bt.w;
        int o = i * 4;  // aligned; whole float4 is in one third
        if (o < D_ || o >= 2 * D_) {
            y.x = sigmoidf_(y.x);
            y.y = sigmoidf_(y.y);
            y.z = sigmoidf_(y.z);
            y.w = sigmoidf_(y.w);
        }
        ((float4*)orow)[i] = y;
    }
}

// ---------------------------------------------------------------------------
// Kernel 3: linear recurrence scan (fwd for c<D/2, bwd for c>=D/2) + combine.
// One thread per (b, c) channel: 16384 threads.
//   h[t] = (1-g)*h_prev + g*x ;  out = (1-hg)*h + input*hg
// ---------------------------------------------------------------------------
__global__ __launch_bounds__(256) void scan_combine_kernel(const float* __restrict__ input,
                                                           float* __restrict__ out) {
    const int ch = blockIdx.x * blockDim.x + threadIdx.x;
    if (ch >= B_ * D_) return;
    const int b = ch >> 10;       // / D_
    const int c = ch & (D_ - 1);  // % D_

    const size_t stride3 = (size_t)B_ * N_;   // per-t stride in g_post
    const size_t stride1 = (size_t)B_ * D_;   // per-t stride in input/out
    const size_t base3 = (size_t)b * N_ + c;
    const size_t base1 = (size_t)b * D_ + c;

    float h = 0.f;
    if (c < D_ / 2) {
#pragma unroll 4
        for (int t = 0; t < T_; t++) {
            size_t r3 = base3 + (size_t)t * stride3;
            size_t r1 = base1 + (size_t)t * stride1;
            float g = g_post[r3];
            float x = g_post[r3 + D_];
            float hg = g_post[r3 + 2 * D_];
            float inp = input[r1];
            h = (1.f - g) * h + g * x;
            out[r1] = (1.f - hg) * h + inp * hg;
        }
    } else {
#pragma unroll 4
        for (int t = T_ - 1; t >= 0; t--) {
            size_t r3 = base3 + (size_t)t * stride3;
            size_t r1 = base1 + (size_t)t * stride1;
            float g = g_post[r3];
            float x = g_post[r3 + D_];
            float hg = g_post[r3 + 2 * D_];
            float inp = input[r1];
            h = (1.f - g) * h + g * x;
            out[r1] = (1.f - hg) * h + inp * hg;
        }
    }
}

// ---------------------------------------------------------------------------
extern "C" void kernel_launch(void* const* d_in, const int* in_sizes, int n_in,
                              void* d_out, int out_size) {
    const float* input = (const float*)d_in[0];   // (T, B, D)
    const float* W     = (const float*)d_in[1];   // (D, 3D)
    const float* gamma = (const float*)d_in[2];   // (3D,)
    const float* beta  = (const float*)d_in[3];   // (3D,)
    float* out = (float*)d_out;                   // (T, B, D)

    dim3 ggrid(N_ / 128, M_ / 128);               // 24 x 256
    sgemm_kernel<<<ggrid, 256>>>(input, W);

    ln_act_kernel<<<M_, 256>>>(gamma, beta);

    scan_combine_kernel<<<(B_ * D_ + 255) / 256, 256>>>(input, out);
}

// round 3
// speedup vs baseline: 1.9578x; 1.9578x over previous
#include <cuda_runtime.h>
#include <cuda_bf16.h>
#include <cstdint>

// Problem constants
static constexpr int T_ = 2048;
static constexpr int B_ = 16;
static constexpr int D_ = 1024;
static constexpr int M_ = T_ * B_;    // 32768 rows
static constexpr int N_ = 3 * D_;     // 3072 cols
static constexpr int K_ = D_;         // 1024
static constexpr int K3_ = 3 * K_;    // 3072 (split-precision packed K)
static constexpr float EPS_ = 1e-5f;

// Scratch (__device__ globals; runtime allocation is forbidden)
__device__ __nv_bfloat16 g_A2[(size_t)M_ * K3_];   // [hi | hi | lo]  ~201 MB
__device__ __nv_bfloat16 g_B2[(size_t)K3_ * N_];   // [hi | lo | hi]  ~19 MB
__device__ float g_pre[(size_t)M_ * N_];           // ~402 MB
__device__ float g_post[(size_t)M_ * N_];          // ~402 MB

// ---------------------------------------------------------------------------
// Kernel 0a: split input fp32 -> bf16 (hi, hi, lo) packed along K'
// ---------------------------------------------------------------------------
__global__ __launch_bounds__(256) void convert_A_kernel(const float* __restrict__ in) {
    size_t i = (size_t)blockIdx.x * blockDim.x + threadIdx.x;
    if (i >= (size_t)M_ * K_) return;
    int m = (int)(i >> 10);          // / K_
    int k = (int)(i & (K_ - 1));     // % K_
    float x = in[i];
    __nv_bfloat16 hi = __float2bfloat16(x);
    __nv_bfloat16 lo = __float2bfloat16(x - __bfloat162float(hi));
    size_t base = (size_t)m * K3_;
    g_A2[base + k]          = hi;
    g_A2[base + K_ + k]     = hi;
    g_A2[base + 2 * K_ + k] = lo;
}

// Kernel 0b: split W fp32 -> bf16 (hi, lo, hi) packed along K'
__global__ __launch_bounds__(256) void convert_W_kernel(const float* __restrict__ Wp) {
    size_t i = (size_t)blockIdx.x * blockDim.x + threadIdx.x;
    if (i >= (size_t)K_ * N_) return;
    int k = (int)(i / N_);
    int n = (int)(i % N_);
    float x = Wp[i];
    __nv_bfloat16 hi = __float2bfloat16(x);
    __nv_bfloat16 lo = __float2bfloat16(x - __bfloat162float(hi));
    g_B2[(size_t)k * N_ + n]            = hi;
    g_B2[(size_t)(K_ + k) * N_ + n]     = lo;
    g_B2[(size_t)(2 * K_ + k) * N_ + n] = hi;
}

// ---------------------------------------------------------------------------
// Kernel 1: bf16 tensor-core GEMM  g_pre = A2(MxK') * B2(K'xN), fp32 accum.
// 128x128x32 block tile, 8 warps (4x2), 32x64 warp tiles, mma.sync m16n8k16,
// cp.async double-buffered smem, ldmatrix fragments.
// ---------------------------------------------------------------------------
#define CP_ASYNC16(dst, src) \
    asm volatile("cp.async.cg.shared.global [%0], [%1], 16;\n" :: "r"(dst), "l"(src))
#define CP_COMMIT() asm volatile("cp.async.commit_group;\n" ::)
#define CP_WAIT1()  asm volatile("cp.async.wait_group 1;\n" ::)
#define CP_WAIT0()  asm volatile("cp.async.wait_group 0;\n" ::)

#define LDSM4(R0, R1, R2, R3, addr)                                          \
    asm volatile("ldmatrix.sync.aligned.m8n8.x4.shared.b16 {%0,%1,%2,%3}, [%4];\n" \
                 : "=r"(R0), "=r"(R1), "=r"(R2), "=r"(R3) : "r"(addr))
#define LDSM4T(R0, R1, R2, R3, addr)                                         \
    asm volatile("ldmatrix.sync.aligned.m8n8.x4.trans.shared.b16 {%0,%1,%2,%3}, [%4];\n" \
                 : "=r"(R0), "=r"(R1), "=r"(R2), "=r"(R3) : "r"(addr))
#define MMA16816(C, A0, A1, A2r, A3, B0, B1)                                 \
    asm volatile("mma.sync.aligned.m16n8k16.row.col.f32.bf16.bf16.f32 "      \
                 "{%0,%1,%2,%3},{%4,%5,%6,%7},{%8,%9},{%0,%1,%2,%3};\n"      \
                 : "+f"(C[0]), "+f"(C[1]), "+f"(C[2]), "+f"(C[3])            \
                 : "r"(A0), "r"(A1), "r"(A2r), "r"(A3), "r"(B0), "r"(B1))

__global__ __launch_bounds__(256) void mma_gemm_kernel() {
    constexpr int BM = 128, BN = 128, BK = 32;
    constexpr int KTILES = K3_ / BK;                 // 96
    constexpr int APAD = 8, BPAD = 8;                // pad -> conflict-free ldmatrix
    __shared__ __nv_bfloat16 As[2][BM][BK + APAD];   // 2*128*40*2B = 20 KB
    __shared__ __nv_bfloat16 Bs[2][BK][BN + BPAD];   // 2*32*136*2B ~ 17.4 KB

    const int tid  = threadIdx.x;
    const int lane = tid & 31;
    const int warp = tid >> 5;
    const int wm = warp & 3, wn = warp >> 2;         // 4 x 2 warp grid
    const int m0 = wm * 32, n0 = wn * 64;
    const int bx = blockIdx.x, by = blockIdx.y;

    const __nv_bfloat16* Ag = g_A2 + (size_t)by * BM * K3_;
    const __nv_bfloat16* Bg = g_B2 + (size_t)bx * BN;

    const uint32_t as_base = (uint32_t)__cvta_generic_to_shared(&As[0][0][0]);
    const uint32_t bs_base = (uint32_t)__cvta_generic_to_shared(&Bs[0][0][0]);
    constexpr uint32_t AS_STAGE = BM * (BK + APAD) * 2;   // bytes
    constexpr uint32_t BS_STAGE = BK * (BN + BPAD) * 2;

    // per-thread cooperative-load coords (2 x 16B chunks for A and for B)
    const int a_r0 = tid >> 2,  a_c0 = (tid & 3) * 8;
    const int b_r0 = tid >> 4,  b_c0 = (tid & 15) * 8;

    float acc[2][8][4];
#pragma unroll
    for (int i = 0; i < 2; i++)
#pragma unroll
        for (int j = 0; j < 8; j++)
#pragma unroll
            for (int v = 0; v < 4; v++) acc[i][j][v] = 0.f;

    auto load_tiles = [&](int kt, int stage) {
        const int k0 = kt * BK;
#pragma unroll
        for (int i = 0; i < 2; i++) {
            int ar = a_r0 + i * 64;      // chunk = tid + i*256 -> row += 64
            uint32_t da = as_base + stage * AS_STAGE + (ar * (BK + APAD) + a_c0) * 2;
            CP_ASYNC16(da, Ag + (size_t)ar * K3_ + k0 + a_c0);
            int br = b_r0 + i * 16;      // row += 16
            uint32_t db = bs_base + stage * BS_STAGE + (br * (BN + BPAD) + b_c0) * 2;
            CP_ASYNC16(db, Bg + (size_t)(k0 + br) * N_ + b_c0);
        }
        CP_COMMIT();
    };

    load_tiles(0, 0);

    const int lrow = lane & 15;          // ldmatrix row within 16
    const int lsel = lane >> 4;          // 0/1 -> +8 column half

    for (int kt = 0; kt < KTILES; kt++) {
        const int stage = kt & 1;
        if (kt + 1 < KTILES) { load_tiles(kt + 1, stage ^ 1); CP_WAIT1(); }
        else                 { CP_WAIT0(); }
        __syncthreads();

#pragma unroll
        for (int kk = 0; kk < BK; kk += 16) {
            uint32_t a[2][4];
#pragma unroll
            for (int im = 0; im < 2; im++) {
                uint32_t addr = as_base + stage * AS_STAGE +
                                ((m0 + im * 16 + lrow) * (BK + APAD) + kk + 8 * lsel) * 2;
                LDSM4(a[im][0], a[im][1], a[im][2], a[im][3], addr);
            }
#pragma unroll
            for (int jn = 0; jn < 4; jn++) {
                uint32_t b0, b1, b2, b3;
                uint32_t addr = bs_base + stage * BS_STAGE +
                                ((kk + lrow) * (BN + BPAD) + n0 + jn * 16 + 8 * lsel) * 2;
                LDSM4T(b0, b1, b2, b3, addr);
                MMA16816(acc[0][2 * jn],     a[0][0], a[0][1], a[0][2], a[0][3], b0, b1);
                MMA16816(acc[0][2 * jn + 1], a[0][0], a[0][1], a[0][2], a[0][3], b2, b3);
                MMA16816(acc[1][2 * jn],     a[1][0], a[1][1], a[1][2], a[1][3], b0, b1);
                MMA16816(acc[1][2 * jn + 1], a[1][0], a[1][1], a[1][2], a[1][3], b2, b3);
            }
        }
        __syncthreads();
    }

    // Epilogue: write fp32 to g_pre
    const int gid = lane >> 2, tig = lane & 3;
#pragma unroll
    for (int im = 0; im < 2; im++) {
#pragma unroll
        for (int jn = 0; jn < 8; jn++) {
            int r = by * BM + m0 + im * 16 + gid;
            int c = bx * BN + n0 + jn * 8 + 2 * tig;
            float* p = g_pre + (size_t)r * N_ + c;
            *(float2*)p            = make_float2(acc[im][jn][0], acc[im][jn][1]);
            *(float2*)(p + 8 * N_) = make_float2(acc[im][jn][2], acc[im][jn][3]);
        }
    }
}

// ---------------------------------------------------------------------------
// Kernel 2: LayerNorm over last dim (3072) + affine + sigmoid on thirds 0, 2.
// ---------------------------------------------------------------------------
__device__ __forceinline__ float sigmoidf_(float y) {
    return 1.f / (1.f + __expf(-y));
}

__global__ __launch_bounds__(256) void ln_act_kernel(const float* __restrict__ gamma,
                                                     const float* __restrict__ beta) {
    const int r = blockIdx.x;
    const float* row = g_pre + (size_t)r * N_;
    float* orow = g_post + (size_t)r * N_;

    float sum = 0.f, sumsq = 0.f;
    for (int i = threadIdx.x; i < N_ / 4; i += 256) {
        float4 v = ((const float4*)row)[i];
        sum += v.x + v.y + v.z + v.w;
        sumsq += v.x * v.x + v.y * v.y + v.z * v.z + v.w * v.w;
    }
    __shared__ float s1[32], s2[32];
#pragma unroll
    for (int o = 16; o; o >>= 1) {
        sum += __shfl_down_sync(~0u, sum, o);
        sumsq += __shfl_down_sync(~0u, sumsq, o);
    }
    int w = threadIdx.x >> 5, l = threadIdx.x & 31;
    if (!l) { s1[w] = sum; s2[w] = sumsq; }
    __syncthreads();
    if (w == 0) {
        sum = (l < 8) ? s1[l] : 0.f;
        sumsq = (l < 8) ? s2[l] : 0.f;
#pragma unroll
        for (int o = 4; o; o >>= 1) {
            sum += __shfl_down_sync(~0u, sum, o);
            sumsq += __shfl_down_sync(~0u, sumsq, o);
        }
        if (!l) {
            float mu = sum * (1.f / N_);
            float var = sumsq * (1.f / N_) - mu * mu;
            s1[0] = mu;
            s2[0] = rsqrtf(var + EPS_);
        }
    }
    __syncthreads();
    const float mu = s1[0], inv = s2[0];

    for (int i = threadIdx.x; i < N_ / 4; i += 256) {
        float4 v = ((const float4*)row)[i];
        float4 gm = ((const float4*)gamma)[i];
        float4 bt = ((const float4*)beta)[i];
        float4 y;
        y.x = (v.x - mu) * inv * gm.x + bt.x;
        y.y = (v.y - mu) * inv * gm.y + bt.y;
        y.z = (v.z - mu) * inv * gm.z + bt.z;
        y.w = (v.w - mu) * inv * gm.w + bt.w;
        int o = i * 4;  // whole float4 lies in one third
        if (o < D_ || o >= 2 * D_) {
            y.x = sigmoidf_(y.x);
            y.y = sigmoidf_(y.y);
            y.z = sigmoidf_(y.z);
            y.w = sigmoidf_(y.w);
        }
        ((float4*)orow)[i] = y;
    }
}

// ---------------------------------------------------------------------------
// Kernel 3: linear recurrence scan (fwd c<D/2, bwd c>=D/2) + output combine.
// ---------------------------------------------------------------------------
__global__ __launch_bounds__(256) void scan_combine_kernel(const float* __restrict__ input,
                                                           float* __restrict__ out) {
    const int ch = blockIdx.x * blockDim.x + threadIdx.x;
    if (ch >= B_ * D_) return;
    const int b = ch >> 10;
    const int c = ch & (D_ - 1);

    const size_t stride3 = (size_t)B_ * N_;
    const size_t stride1 = (size_t)B_ * D_;
    const size_t base3 = (size_t)b * N_ + c;
    const size_t base1 = (size_t)b * D_ + c;

    float h = 0.f;
    if (c < D_ / 2) {
#pragma unroll 4
        for (int t = 0; t < T_; t++) {
            size_t r3 = base3 + (size_t)t * stride3;
            size_t r1 = base1 + (size_t)t * stride1;
            float g = g_post[r3];
            float x = g_post[r3 + D_];
            float hg = g_post[r3 + 2 * D_];
            float inp = input[r1];
            h = (1.f - g) * h + g * x;
            out[r1] = (1.f - hg) * h + inp * hg;
        }
    } else {
#pragma unroll 4
        for (int t = T_ - 1; t >= 0; t--) {
            size_t r3 = base3 + (size_t)t * stride3;
            size_t r1 = base1 + (size_t)t * stride1;
            float g = g_post[r3];
            float x = g_post[r3 + D_];
            float hg = g_post[r3 + 2 * D_];
            float inp = input[r1];
            h = (1.f - g) * h + g * x;
            out[r1] = (1.f - hg) * h + inp * hg;
        }
    }
}

// ---------------------------------------------------------------------------
extern "C" void kernel_launch(void* const* d_in, const int* in_sizes, int n_in,
                              void* d_out, int out_size) {
    const float* input = (const float*)d_in[0];   // (T, B, D)
    const float* W     = (const float*)d_in[1];   // (D, 3D)
    const float* gamma = (const float*)d_in[2];   // (3D,)
    const float* beta  = (const float*)d_in[3];   // (3D,)
    float* out = (float*)d_out;                   // (T, B, D)

    convert_A_kernel<<<(int)(((size_t)M_ * K_ + 255) / 256), 256>>>(input);
    convert_W_kernel<<<(int)(((size_t)K_ * N_ + 255) / 256), 256>>>(W);

    dim3 ggrid(N_ / 128, M_ / 128);               // 24 x 256
    mma_gemm_kernel<<<ggrid, 256>>>();

    ln_act_kernel<<<M_, 256>>>(gamma, beta);

    scan_combine_kernel<<<(B_ * D_ + 255) / 256, 256>>>(input, out);
}